// round 15
// baseline (speedup 1.0000x reference)
#include <cuda_runtime.h>
#include <cstdint>
#include <cstddef>

// ---------------- Problem dims ----------------
#define LDIM 2
#define BDIM 16384
#define SDIM 512
#define N4   2048

// ---------------- GEMM tiling ----------------
// N-tile = 4 gates x 32 s-positions (gate-gathered columns).
#define TILE_M 128
#define TILE_N 128
#define SSTRIP 32
#define BK     32
#define NCHUNK 32          // 2 operand pairs * (512/32)
#define NSTAGE 3

// SMEM (floats): A pitch 36 (bank = lane, conflict-free), B pitch 136.
#define APITCH 36
#define BPITCH 136
#define A_FLOATS (TILE_M * APITCH)     // 4608
#define B_FLOATS (BK * BPITCH)         // 4352
#define STAGE_FLOATS (A_FLOATS + B_FLOATS)            // 8960
#define SMEM_TOTAL (NSTAGE * STAGE_FLOATS * 4)        // 107520 bytes

// ---------------- helpers ----------------
__device__ __forceinline__ uint32_t smem_u32(const void* p) {
    uint32_t a;
    asm("{ .reg .u64 t; cvta.to.shared.u64 t, %1; cvt.u32.u64 %0, t; }" : "=r"(a) : "l"(p));
    return a;
}
__device__ __forceinline__ void cp16(uint32_t s, const void* g) {
    asm volatile("cp.async.cg.shared.global [%0], [%1], 16;" :: "r"(s), "l"(g) : "memory");
}
__device__ __forceinline__ void cp_commit() {
    asm volatile("cp.async.commit_group;" ::: "memory");
}
__device__ __forceinline__ void cp_wait1() {
    asm volatile("cp.async.wait_group 1;" ::: "memory");
}
__device__ __forceinline__ void cp_wait0() {
    asm volatile("cp.async.wait_group 0;" ::: "memory");
}
// m16n8k8 tf32 warp MMA (fp32 inputs truncated to tf32 by HW)
__device__ __forceinline__ void mma8(float* d, const uint32_t* a, const uint32_t* b) {
    asm volatile(
        "mma.sync.aligned.m16n8k8.row.col.f32.tf32.tf32.f32 "
        "{%0,%1,%2,%3}, {%4,%5,%6,%7}, {%8,%9}, {%10,%11,%12,%13};"
        : "=f"(d[0]), "=f"(d[1]), "=f"(d[2]), "=f"(d[3])
        : "r"(a[0]), "r"(a[1]), "r"(a[2]), "r"(a[3]),
          "r"(b[0]), "r"(b[1]),
          "f"(d[0]), "f"(d[1]), "f"(d[2]), "f"(d[3]));
}
// fast sigmoid / tanh via MUFU ex2 (saturation-safe)
__device__ __forceinline__ float fsig(float x)  { return 1.f / (1.f + __expf(-x)); }
__device__ __forceinline__ float ftanh(float x) { return 2.f / (1.f + __expf(-2.f * x)) - 1.f; }

// ---------------- tile staging ----------------
// B columns are gate-gathered: tile col = gate*32 + s_local, global col = gate*512 + s0 + s_local
__device__ __forceinline__ void stage(uint32_t sbase, int slot,
                                      const float* __restrict__ Ab,
                                      const float* __restrict__ Bb,
                                      int m0, int s0, int k0, int tid)
{
    const uint32_t sa = sbase + (uint32_t)(slot * STAGE_FLOATS) * 4u;
    const uint32_t sb = sa + (uint32_t)A_FLOATS * 4u;
    // A tile: 128 rows x 32 k  -> 1024 float4, 8 per thread
#pragma unroll
    for (int i = 0; i < 8; ++i) {
        const int v = tid + i * 128;
        const int m = v >> 3, kv = v & 7;
        cp16(sa + (uint32_t)(m * APITCH + kv * 4) * 4u,
             Ab + (size_t)(m0 + m) * SDIM + k0 + kv * 4);
    }
    // B tile: 32 k-rows x 128 gathered cols -> 1024 float4, 8 per thread
#pragma unroll
    for (int i = 0; i < 8; ++i) {
        const int v = tid + i * 128;
        const int k = v >> 5, j = v & 31;           // j = vector within row (0..31)
        const int gate = j >> 3;                    // 8 vectors per 32-col strip
        const int off  = (j & 7) * 4;
        cp16(sb + (uint32_t)(k * BPITCH + j * 4) * 4u,
             Bb + (size_t)(k0 + k) * N4 + gate * SDIM + s0 + off);
    }
}

// ---------------- per-chunk compute (warp tile 32x128) ----------------
__device__ __forceinline__ void compute_chunk(const float* __restrict__ As,
                                              const float* __restrict__ Bs,
                                              float (&acc)[2][16][4],
                                              int lane, int wm)
{
#pragma unroll
    for (int ks = 0; ks < 4; ++ks) {
        const int ka = ks * 8 + (lane & 3);
        const int ra = wm + (lane >> 2);
        uint32_t a[2][4];
#pragma unroll
        for (int mt = 0; mt < 2; ++mt) {
            const float* ap = As + (size_t)(ra + mt * 16) * APITCH + ka;
            a[mt][0] = __float_as_uint(ap[0]);
            a[mt][1] = __float_as_uint(ap[8 * APITCH]);
            a[mt][2] = __float_as_uint(ap[4]);
            a[mt][3] = __float_as_uint(ap[8 * APITCH + 4]);
        }
        uint32_t b[16][2];
        const int kb = ks * 8 + (lane & 3);
        const int nb = lane >> 2;
#pragma unroll
        for (int nt = 0; nt < 16; ++nt) {
            const float* bp = Bs + (size_t)kb * BPITCH + nb + nt * 8;
            b[nt][0] = __float_as_uint(bp[0]);
            b[nt][1] = __float_as_uint(bp[4 * BPITCH]);
        }
#pragma unroll
        for (int mt = 0; mt < 2; ++mt)
#pragma unroll
            for (int nt = 0; nt < 16; ++nt)
                mma8(acc[mt][nt], a[mt], b[nt]);
    }
}

// ---------------- fused dual-GEMM + LSTM gates ----------------
// z = X@W + H@U + bias (tf32 MMA), then per-element:
//   c = sig(zf)*c_prev + sig(zi)*tanh(zg);  h = sig(zo)*tanh(c)
__global__ __launch_bounds__(128, 2)
void lstm_fused(const float* __restrict__ A1, const float* __restrict__ A2,
                const float* __restrict__ Bw, const float* __restrict__ Bu,
                const float* __restrict__ bias,
                const float* __restrict__ c_prev,
                float* __restrict__ h_out, float* __restrict__ c_out)
{
    extern __shared__ float sm[];
    const uint32_t sbase = smem_u32(sm);
    const int tid  = threadIdx.x;
    const int lane = tid & 31;
    const int warp = tid >> 5;
    const int wm = warp * 32;                   // warp rows [wm, wm+32)
    const int m0 = blockIdx.y * TILE_M;
    const int s0 = blockIdx.x * SSTRIP;         // s-strip [s0, s0+32)

    float acc[2][16][4];
#pragma unroll
    for (int mt = 0; mt < 2; ++mt)
#pragma unroll
        for (int nt = 0; nt < 16; ++nt)
#pragma unroll
            for (int r = 0; r < 4; ++r)
                acc[mt][nt][r] = 0.f;

    // prologue: stage chunks 0 and 1
    stage(sbase, 0, A1, Bw, m0, s0, 0, tid);
    cp_commit();
    stage(sbase, 1, A1, Bw, m0, s0, BK, tid);
    cp_commit();

#pragma unroll 1
    for (int c = 0; c < NCHUNK; ++c) {
        if (c >= NCHUNK - 2) cp_wait0(); else cp_wait1();   // chunk c resident
        __syncthreads();                                     // readers of slot (c+2)%3 done
        if (c + 2 < NCHUNK) {
            const int cn = c + 2;
            stage(sbase, cn % NSTAGE,
                  (cn < 16) ? A1 : A2, (cn < 16) ? Bw : Bu,
                  m0, s0, (cn & 15) * BK, tid);
            cp_commit();
        }
        const float* st = sm + (c % NSTAGE) * STAGE_FLOATS;
        compute_chunk(st, st + A_FLOATS, acc, lane, wm);
    }

    // ---- fused epilogue: gates in registers ----
    // acc[mt][nt][0..1] -> row r0,  cols cc..cc+1 ; acc[mt][nt][2..3] -> row r0+8
    // gate g of s-position (s0 + nt*8 + cc) lives at nt + 4*g  (nt in 0..3)
    const int r0 = lane >> 2;
    const int cc = (lane & 3) * 2;
#pragma unroll
    for (int mt = 0; mt < 2; ++mt) {
#pragma unroll
        for (int nt = 0; nt < 4; ++nt) {
            const int s = s0 + nt * 8 + cc;
            const float2 bi = *reinterpret_cast<const float2*>(bias + s);
            const float2 bf = *reinterpret_cast<const float2*>(bias + SDIM + s);
            const float2 bg = *reinterpret_cast<const float2*>(bias + 2 * SDIM + s);
            const float2 bo = *reinterpret_cast<const float2*>(bias + 3 * SDIM + s);
#pragma unroll
            for (int rr = 0; rr < 2; ++rr) {
                const int m = m0 + wm + mt * 16 + r0 + rr * 8;
                const float2 cp = *reinterpret_cast<const float2*>(
                    c_prev + (size_t)m * SDIM + s);
                const float zi0 = acc[mt][nt     ][rr * 2 + 0] + bi.x;
                const float zi1 = acc[mt][nt     ][rr * 2 + 1] + bi.y;
                const float zf0 = acc[mt][nt +  4][rr * 2 + 0] + bf.x;
                const float zf1 = acc[mt][nt +  4][rr * 2 + 1] + bf.y;
                const float zg0 = acc[mt][nt +  8][rr * 2 + 0] + bg.x;
                const float zg1 = acc[mt][nt +  8][rr * 2 + 1] + bg.y;
                const float zo0 = acc[mt][nt + 12][rr * 2 + 0] + bo.x;
                const float zo1 = acc[mt][nt + 12][rr * 2 + 1] + bo.y;

                float2 cv, hv;
                cv.x = fsig(zf0) * cp.x + fsig(zi0) * ftanh(zg0);
                cv.y = fsig(zf1) * cp.y + fsig(zi1) * ftanh(zg1);
                hv.x = fsig(zo0) * ftanh(cv.x);
                hv.y = fsig(zo1) * ftanh(cv.y);

                *reinterpret_cast<float2*>(c_out + (size_t)m * SDIM + s) = cv;
                *reinterpret_cast<float2*>(h_out + (size_t)m * SDIM + s) = hv;
            }
        }
    }
}

// ---------------- launch ----------------
extern "C" void kernel_launch(void* const* d_in, const int* in_sizes, int n_in,
                              void* d_out, int out_size)
{
    const float* inputs  = (const float*)d_in[0];  // [B, S]
    const float* prev_c  = (const float*)d_in[1];  // [L, B, S] -> h_tm1 (NNI swap)
    const float* prev_h  = (const float*)d_in[2];  // [L, B, S] -> c_tm1 (NNI swap)
    const float* kernels = (const float*)d_in[3];  // [L, S, 4S]
    const float* rec_k   = (const float*)d_in[4];  // [L, S, 4S]
    const float* biases  = (const float*)d_in[5];  // [L, 4S]
    float* out = (float*)d_out;                    // [L, 2, B, S]

    const size_t BS     = (size_t)BDIM * SDIM;      // 8,388,608
    const size_t WLAYER = (size_t)SDIM * N4;        // 1,048,576

    cudaFuncSetAttribute(lstm_fused,
                         cudaFuncAttributeMaxDynamicSharedMemorySize, SMEM_TOTAL);

    const dim3 grid(SDIM / SSTRIP, BDIM / TILE_M);  // (16, 128)

    // ---- Layer 0 ----  h0 -> out[0,0], c0 -> out[0,1]
    lstm_fused<<<grid, 128, SMEM_TOTAL>>>(inputs, prev_c,
                                          kernels, rec_k, biases,
                                          prev_h, out, out + BS);

    // ---- Layer 1 ----  input x = c0 = out[0,1]
    lstm_fused<<<grid, 128, SMEM_TOTAL>>>(out + BS, prev_c + BS,
                                          kernels + WLAYER, rec_k + WLAYER,
                                          biases + N4,
                                          prev_h + BS, out + 2 * BS, out + 3 * BS);
}